// round 16
// baseline (speedup 1.0000x reference)
#include <cuda_runtime.h>
#include <cstdint>

// Zero-initialized device global (no allocations allowed).
// Single packed word: bits[0:16)=block arrival count, bits[16:32)=count of
// blocks seeing any((x+1)+1 >= 3), bits[32:48)=count of blocks seeing
// any(4-adds >= 3). One relaxed 64-bit atomicAdd per block carries BOTH the
// flags and the arrival; the last arriver reconstructs final flags from
// (old + own delta). Last block runs the (statistically never-taken) fixup
// and resets the word, keeping every graph replay deterministic.
//
// R16 experiment: double instantaneous address spread — 2048 blocks x 128
// threads, dense 8 KB chunks (vs the 1024 x 256 / 16 KB optimum at 37.9-38.4
// us). Everything else held at the measured-best settings:
//  - strided dense chunks, UNROLL=4, no cache hints,
//  - block-level relaxed packed atomic arrival,
//  - exact 8 chunks/block balance (16384 / 2048).
__device__ unsigned long long g_packed;

#define THREADS 128
#define WARPS   (THREADS / 32)
#define UNROLL  4
#define CHUNK   (THREADS * UNROLL)   // 512 float4 = 8 KB per block-iteration
#define BLOCKS  2048                 // 16384 chunks / 2048 = exactly 8 chunks/block

#define A_INC (1ULL << 16)
#define B_INC (1ULL << 32)

__global__ void __launch_bounds__(THREADS) scn_fused_kernel(
    const float4* __restrict__ x, float4* __restrict__ out, int n4)
{
    const int t = threadIdx.x;

    // Running max of o = (x+1)+1 over this thread's elements.
    float m = -3.402823466e+38f;

    const int nchunks = n4 / CHUNK;          // 8388608 / 512 = 16384 (exact)

    // Strided chunk assignment: block b handles chunks b, b+grid, b+2*grid, ...
    for (int c = blockIdx.x; c < nchunks; c += gridDim.x) {
        const int base = c * CHUNK + t;

        // 4 independent coalesced LDG.128 within one dense 8 KB chunk.
        float4 v0 = x[base];
        float4 v1 = x[base + THREADS];
        float4 v2 = x[base + 2 * THREADS];
        float4 v3 = x[base + 3 * THREADS];

        float4 o0, o1, o2, o3;
        o0.x = (v0.x + 1.0f) + 1.0f;  o0.y = (v0.y + 1.0f) + 1.0f;
        o0.z = (v0.z + 1.0f) + 1.0f;  o0.w = (v0.w + 1.0f) + 1.0f;
        o1.x = (v1.x + 1.0f) + 1.0f;  o1.y = (v1.y + 1.0f) + 1.0f;
        o1.z = (v1.z + 1.0f) + 1.0f;  o1.w = (v1.w + 1.0f) + 1.0f;
        o2.x = (v2.x + 1.0f) + 1.0f;  o2.y = (v2.y + 1.0f) + 1.0f;
        o2.z = (v2.z + 1.0f) + 1.0f;  o2.w = (v2.w + 1.0f) + 1.0f;
        o3.x = (v3.x + 1.0f) + 1.0f;  o3.y = (v3.y + 1.0f) + 1.0f;
        o3.z = (v3.z + 1.0f) + 1.0f;  o3.w = (v3.w + 1.0f) + 1.0f;

        float ma = fmaxf(fmaxf(o0.x, o0.y), fmaxf(o0.z, o0.w));
        float mb = fmaxf(fmaxf(o1.x, o1.y), fmaxf(o1.z, o1.w));
        float mc = fmaxf(fmaxf(o2.x, o2.y), fmaxf(o2.z, o2.w));
        float md = fmaxf(fmaxf(o3.x, o3.y), fmaxf(o3.z, o3.w));
        m = fmaxf(m, fmaxf(fmaxf(ma, mb), fmaxf(mc, md)));

        out[base]               = o0;
        out[base + THREADS]     = o1;
        out[base + 2 * THREADS] = o2;
        out[base + 3 * THREADS] = o3;
    }

    // Generic tail for non-multiple-of-CHUNK sizes (empty for this shape).
    for (int i = nchunks * CHUNK + blockIdx.x * THREADS + t; i < n4;
         i += gridDim.x * THREADS) {
        float4 v = x[i];
        float4 o;
        o.x = (v.x + 1.0f) + 1.0f;  o.y = (v.y + 1.0f) + 1.0f;
        o.z = (v.z + 1.0f) + 1.0f;  o.w = (v.w + 1.0f) + 1.0f;
        m = fmaxf(m, fmaxf(fmaxf(o.x, o.y), fmaxf(o.z, o.w)));
        out[i] = o;
    }

    // fp add of a constant is monotone non-decreasing, so (bit-exact):
    //   any((o+1)+1 >= 3)  <=>  ((max(o)+1)+1) >= 3
    bool ta = (m >= 3.0f);
    bool tb = (((m + 1.0f) + 1.0f) >= 3.0f);

    unsigned wa = __any_sync(0xFFFFFFFFu, ta);
    unsigned wb = __any_sync(0xFFFFFFFFu, tb);

    __shared__ unsigned char s_wf[WARPS];
    __shared__ unsigned long long s_final;  // final packed value, 0 if not last
    if ((t & 31) == 0)
        s_wf[t >> 5] = (unsigned char)((wa ? 1u : 0u) | (wb ? 2u : 0u));
    __syncthreads();

    if (t == 0) {
        unsigned f = 0;
#pragma unroll
        for (int w = 0; w < WARPS; w++) f |= s_wf[w];
        unsigned long long delta = 1ULL
                                 + ((f & 1u) ? A_INC : 0ULL)
                                 + ((f & 2u) ? B_INC : 0ULL);
        unsigned long long old = atomicAdd(&g_packed, delta);
        unsigned arrivals = (unsigned)(old & 0xFFFFULL) + 1u;
        s_final = (arrivals == gridDim.x) ? (old + delta) : 0ULL;
    }
    __syncthreads();

    unsigned long long fin = s_final;
    if (fin) {
        // Last-arriving block. All other blocks' deltas are in `fin`.
        bool any_a = ((fin >> 16) & 0xFFFFULL) != 0;
        bool any_b = ((fin >> 32) & 0xFFFFULL) != 0;

        if (!any_a) {
            // Rare path (statistically never for this input: requires ALL
            // 33.5M N(0,1) samples < 1.0): the chain survived checker #1 —
            // rewrite output with deeper-chain values, reading only x.
            bool five = !any_b;
            for (int j = t; j < n4; j += THREADS) {
                float4 v = x[j];
                float4 o;
                o.x = (((v.x + 1.0f) + 1.0f) + 1.0f) + 1.0f;
                o.y = (((v.y + 1.0f) + 1.0f) + 1.0f) + 1.0f;
                o.z = (((v.z + 1.0f) + 1.0f) + 1.0f) + 1.0f;
                o.w = (((v.w + 1.0f) + 1.0f) + 1.0f) + 1.0f;
                if (five) { o.x += 1.0f; o.y += 1.0f; o.z += 1.0f; o.w += 1.0f; }
                out[j] = o;
            }
        }

        // Reset for the next graph replay: all arrivals already happened
        // (we are last); the next launch is ordered by the launch boundary.
        if (t == 0) g_packed = 0ULL;
    }
}

extern "C" void kernel_launch(void* const* d_in, const int* in_sizes, int n_in,
                              void* d_out, int out_size)
{
    const float4* x = (const float4*)d_in[0];
    float4* out = (float4*)d_out;
    int n = in_sizes[0];
    int n4 = n >> 2;  // 4096*8192 divisible by 4

    scn_fused_kernel<<<BLOCKS, THREADS>>>(x, out, n4);
}

// round 17
// speedup vs baseline: 1.0098x; 1.0098x over previous
#include <cuda_runtime.h>
#include <cstdint>

// Zero-initialized device global (no allocations allowed).
// Single packed word: bits[0:16)=block arrival count, bits[16:32)=count of
// blocks seeing any((x+1)+1 >= 3), bits[32:48)=count of blocks seeing
// any(4-adds >= 3). One relaxed 64-bit atomicAdd per block carries BOTH the
// flags and the arrival; the last arriver reconstructs final flags from
// (old + own delta). Last block runs the (statistically never-taken) fixup
// and resets the word, keeping every graph replay deterministic.
//
// FINAL configuration — measured optimum on GB300 over 9 structural variants
// (kernel 37.9-38.4 us across three reproductions, ~7.05 TB/s effective =
// the practical LTS/HBM mixed-stream ceiling; 256 MiB spec floor = 33.5 us):
//  - strided dense 16 KB chunks   (vs 39.4 contiguous, 41.9 scattered)
//  - 1024 blocks x 256 threads, exactly 8 chunks/block (vs 38.4 @ 1184,
//    38.8 @ 2048x128/8KB)
//  - UNROLL=4                     (vs 40.6 @ 1, 40.5 @ 8)
//  - block-level relaxed packed atomic arrival (vs 39.9 warp-level,
//    40.5 fenced two-atomic, 48.3 three-kernel launch)
//  - no cache hints               (vs 39.5 .cs stores, 41.9 both)
__device__ unsigned long long g_packed;

#define THREADS 256
#define WARPS   (THREADS / 32)
#define UNROLL  4
#define CHUNK   (THREADS * UNROLL)   // 1024 float4 = 16 KB per block-iteration
#define BLOCKS  1024                 // 8192 chunks / 1024 = exactly 8 chunks/block

#define A_INC (1ULL << 16)
#define B_INC (1ULL << 32)

__global__ void __launch_bounds__(THREADS) scn_fused_kernel(
    const float4* __restrict__ x, float4* __restrict__ out, int n4)
{
    const int t = threadIdx.x;

    // Running max of o = (x+1)+1 over this thread's elements.
    float m = -3.402823466e+38f;

    const int nchunks = n4 / CHUNK;          // 8388608 / 1024 = 8192 (exact)

    // Strided chunk assignment: block b handles chunks b, b+grid, b+2*grid, ...
    for (int c = blockIdx.x; c < nchunks; c += gridDim.x) {
        const int base = c * CHUNK + t;

        // 4 independent coalesced LDG.128 within one dense 16 KB chunk.
        float4 v0 = x[base];
        float4 v1 = x[base + THREADS];
        float4 v2 = x[base + 2 * THREADS];
        float4 v3 = x[base + 3 * THREADS];

        float4 o0, o1, o2, o3;
        o0.x = (v0.x + 1.0f) + 1.0f;  o0.y = (v0.y + 1.0f) + 1.0f;
        o0.z = (v0.z + 1.0f) + 1.0f;  o0.w = (v0.w + 1.0f) + 1.0f;
        o1.x = (v1.x + 1.0f) + 1.0f;  o1.y = (v1.y + 1.0f) + 1.0f;
        o1.z = (v1.z + 1.0f) + 1.0f;  o1.w = (v1.w + 1.0f) + 1.0f;
        o2.x = (v2.x + 1.0f) + 1.0f;  o2.y = (v2.y + 1.0f) + 1.0f;
        o2.z = (v2.z + 1.0f) + 1.0f;  o2.w = (v2.w + 1.0f) + 1.0f;
        o3.x = (v3.x + 1.0f) + 1.0f;  o3.y = (v3.y + 1.0f) + 1.0f;
        o3.z = (v3.z + 1.0f) + 1.0f;  o3.w = (v3.w + 1.0f) + 1.0f;

        float ma = fmaxf(fmaxf(o0.x, o0.y), fmaxf(o0.z, o0.w));
        float mb = fmaxf(fmaxf(o1.x, o1.y), fmaxf(o1.z, o1.w));
        float mc = fmaxf(fmaxf(o2.x, o2.y), fmaxf(o2.z, o2.w));
        float md = fmaxf(fmaxf(o3.x, o3.y), fmaxf(o3.z, o3.w));
        m = fmaxf(m, fmaxf(fmaxf(ma, mb), fmaxf(mc, md)));

        out[base]               = o0;
        out[base + THREADS]     = o1;
        out[base + 2 * THREADS] = o2;
        out[base + 3 * THREADS] = o3;
    }

    // Generic tail for non-multiple-of-CHUNK sizes (empty for this shape).
    for (int i = nchunks * CHUNK + blockIdx.x * THREADS + t; i < n4;
         i += gridDim.x * THREADS) {
        float4 v = x[i];
        float4 o;
        o.x = (v.x + 1.0f) + 1.0f;  o.y = (v.y + 1.0f) + 1.0f;
        o.z = (v.z + 1.0f) + 1.0f;  o.w = (v.w + 1.0f) + 1.0f;
        m = fmaxf(m, fmaxf(fmaxf(o.x, o.y), fmaxf(o.z, o.w)));
        out[i] = o;
    }

    // fp add of a constant is monotone non-decreasing, so (bit-exact):
    //   any((o+1)+1 >= 3)  <=>  ((max(o)+1)+1) >= 3
    bool ta = (m >= 3.0f);
    bool tb = (((m + 1.0f) + 1.0f) >= 3.0f);

    unsigned wa = __any_sync(0xFFFFFFFFu, ta);
    unsigned wb = __any_sync(0xFFFFFFFFu, tb);

    __shared__ unsigned char s_wf[WARPS];
    __shared__ unsigned long long s_final;  // final packed value, 0 if not last
    if ((t & 31) == 0)
        s_wf[t >> 5] = (unsigned char)((wa ? 1u : 0u) | (wb ? 2u : 0u));
    __syncthreads();

    if (t == 0) {
        unsigned f = 0;
#pragma unroll
        for (int w = 0; w < WARPS; w++) f |= s_wf[w];
        unsigned long long delta = 1ULL
                                 + ((f & 1u) ? A_INC : 0ULL)
                                 + ((f & 2u) ? B_INC : 0ULL);
        unsigned long long old = atomicAdd(&g_packed, delta);
        unsigned arrivals = (unsigned)(old & 0xFFFFULL) + 1u;
        s_final = (arrivals == gridDim.x) ? (old + delta) : 0ULL;
    }
    __syncthreads();

    unsigned long long fin = s_final;
    if (fin) {
        // Last-arriving block. All other blocks' deltas are in `fin`.
        bool any_a = ((fin >> 16) & 0xFFFFULL) != 0;
        bool any_b = ((fin >> 32) & 0xFFFFULL) != 0;

        if (!any_a) {
            // Rare path (statistically never for this input: requires ALL
            // 33.5M N(0,1) samples < 1.0): the chain survived checker #1 —
            // rewrite output with deeper-chain values, reading only x.
            bool five = !any_b;
            for (int j = t; j < n4; j += THREADS) {
                float4 v = x[j];
                float4 o;
                o.x = (((v.x + 1.0f) + 1.0f) + 1.0f) + 1.0f;
                o.y = (((v.y + 1.0f) + 1.0f) + 1.0f) + 1.0f;
                o.z = (((v.z + 1.0f) + 1.0f) + 1.0f) + 1.0f;
                o.w = (((v.w + 1.0f) + 1.0f) + 1.0f) + 1.0f;
                if (five) { o.x += 1.0f; o.y += 1.0f; o.z += 1.0f; o.w += 1.0f; }
                out[j] = o;
            }
        }

        // Reset for the next graph replay: all arrivals already happened
        // (we are last); the next launch is ordered by the launch boundary.
        if (t == 0) g_packed = 0ULL;
    }
}

extern "C" void kernel_launch(void* const* d_in, const int* in_sizes, int n_in,
                              void* d_out, int out_size)
{
    const float4* x = (const float4*)d_in[0];
    float4* out = (float4*)d_out;
    int n = in_sizes[0];
    int n4 = n >> 2;  // 4096*8192 divisible by 4

    scn_fused_kernel<<<BLOCKS, THREADS>>>(x, out, n4);
}